// round 10
// baseline (speedup 1.0000x reference)
#include <cuda_runtime.h>
#include <cstdint>

// Problem constants (B=64, C=512, H=W=28, G=8)
#define HWN   784
#define HW4   196
#define CPG   64
#define NBG   512
#define EPS   1e-5f
#define TILE_FLOATS (CPG * HWN)   // 50176

// scratch for per-tile gates (512 * 784 floats = 1.6 MB)
__device__ float g_gate[NBG * HWN];

// ================= Kernel A: compute sigmoid gate per (b,g) tile =============
__global__ __launch_bounds__(256)
void simam_gate_kernel(const float* __restrict__ x,
                       const float* __restrict__ weight,
                       const float* __restrict__ bias)
{
    __shared__ float s_means[CPG];
    __shared__ float s_red[18];

    const int bg = blockIdx.x;
    const int g  = bg & 7;
    const float* xt = x + (size_t)bg * TILE_FLOATS;

    const int tid  = threadIdx.x;
    const int w    = tid >> 5;
    const int lane = tid & 31;

    // ---- pass 1: per-channel spatial means (DRAM read; fills L2) ----
    #pragma unroll
    for (int i = 0; i < 8; i++) {
        const int c = w + 8 * i;
        const float4* row = (const float4*)(xt + c * HWN);
        float cs = 0.f;
        #pragma unroll
        for (int k = 0; k < 7; k++) {
            const int j = lane + 32 * k;
            if (j < HW4) {
                float4 v = __ldg(row + j);
                cs += (v.x + v.y) + (v.z + v.w);
            }
        }
        #pragma unroll
        for (int o = 16; o; o >>= 1) cs += __shfl_xor_sync(0xffffffffu, cs, o);
        if (lane == 0) s_means[c] = cs * (1.0f / HWN);
    }
    __syncthreads();

    // ---- pass 2: s[hw] = sum_c m_c * x[c,hw]  (tile just read -> L2 hits) ----
    float4 acc = make_float4(0.f, 0.f, 0.f, 0.f);
    float lsum = 0.f, lsq = 0.f;
    if (tid < HW4) {
        const float4* col = (const float4*)xt + tid;    // stride HW4 float4/channel
        #pragma unroll 8
        for (int c = 0; c < CPG; c++) {
            const float  m = s_means[c];
            const float4 v = __ldg(col + c * HW4);
            acc.x += m * v.x;
            acc.y += m * v.y;
            acc.z += m * v.z;
            acc.w += m * v.w;
        }
        lsum = (acc.x + acc.y) + (acc.z + acc.w);
        lsq  = acc.x * acc.x + acc.y * acc.y + acc.z * acc.z + acc.w * acc.w;
    }
    #pragma unroll
    for (int o = 16; o; o >>= 1) {
        lsum += __shfl_xor_sync(0xffffffffu, lsum, o);
        lsq  += __shfl_xor_sync(0xffffffffu, lsq,  o);
    }
    if (lane == 0) { s_red[w] = lsum; s_red[8 + w] = lsq; }
    __syncthreads();
    if (tid == 0) {
        float ts = 0.f, tq = 0.f;
        #pragma unroll
        for (int i = 0; i < 8; i++) { ts += s_red[i]; tq += s_red[8 + i]; }
        const float mu  = ts * (1.0f / HWN);
        const float var = tq * (1.0f / HWN) - mu * mu;
        s_red[16] = mu;
        s_red[17] = rsqrtf(var + EPS);
    }
    __syncthreads();

    // ---- sigmoid gate -> scratch ----
    {
        const float mu = s_red[16];
        const float rs = s_red[17];
        const float wg = weight[g];
        const float bb = bias[g];
        if (tid < HW4) {
            float4 gt;
            gt.x = 1.0f / (1.0f + __expf(-((acc.x - mu) * rs * wg + bb)));
            gt.y = 1.0f / (1.0f + __expf(-((acc.y - mu) * rs * wg + bb)));
            gt.z = 1.0f / (1.0f + __expf(-((acc.z - mu) * rs * wg + bb)));
            gt.w = 1.0f / (1.0f + __expf(-((acc.w - mu) * rs * wg + bb)));
            ((float4*)(g_gate + (size_t)bg * HWN))[tid] = gt;
        }
    }
}

// ================= Kernel B: out = x * gate (elementwise, reverse order) =====
__global__ __launch_bounds__(256)
void simam_apply_kernel(const float* __restrict__ x,
                        float* __restrict__ out)
{
    __shared__ float4 s_g4[HW4];

    const int bg = (int)(gridDim.x - 1 - blockIdx.x);   // reverse: best L2 reuse
    const float* xt = x   + (size_t)bg * TILE_FLOATS;
    float*       ot = out + (size_t)bg * TILE_FLOATS;

    const int tid  = threadIdx.x;
    const int w    = tid >> 5;
    const int lane = tid & 31;

    if (tid < HW4)
        s_g4[tid] = ((const float4*)(g_gate + (size_t)bg * HWN))[tid];
    __syncthreads();

    #pragma unroll
    for (int i = 0; i < 8; i++) {
        const int c = w + 8 * i;
        const float4* xr = (const float4*)(xt + c * HWN);
        float4*       orow = (float4*)(ot + c * HWN);
        #pragma unroll
        for (int k = 0; k < 7; k++) {
            const int j = lane + 32 * k;
            if (j < HW4) {
                float4 v  = __ldg(xr + j);
                float4 gt = s_g4[j];
                v.x *= gt.x; v.y *= gt.y; v.z *= gt.z; v.w *= gt.w;
                orow[j] = v;
            }
        }
    }
}

extern "C" void kernel_launch(void* const* d_in, const int* in_sizes, int n_in,
                              void* d_out, int out_size)
{
    const float* x  = (const float*)d_in[0];
    const float* wt = (const float*)d_in[1];
    const float* bs = (const float*)d_in[2];
    float* out = (float*)d_out;

    simam_gate_kernel<<<NBG, 256>>>(x, wt, bs);
    simam_apply_kernel<<<NBG, 256>>>(x, out);
}

// round 11
// speedup vs baseline: 1.3868x; 1.3868x over previous
#include <cuda_runtime.h>
#include <cstdint>

// Problem constants (B=64, C=512, H=W=28, G=8)
#define HWN    784
#define HW4    196
#define CPG    64
#define EPS    1e-5f
#define NTHR   512
#define NW     16
#define NTILE  512
#define GRID   148

#define HALF_FLOATS (32 * HWN)            // 25088
#define HALF_BYTES  (HALF_FLOATS * 4)     // 100352
#define TILE_FLOATS (CPG * HWN)           // 50176

// smem layout (floats): two contiguous half-buffers form one 64x784 tile
#define OFF_S      TILE_FLOATS            // s / gate (784)
#define OFF_MEANS  (OFF_S + HWN)          // 64
#define OFF_RED    (OFF_MEANS + CPG)      // 36
#define OFF_MBAR   (OFF_RED + 36)         // 2 x u64 (8B aligned: offset*4 % 8 == 0)
#define SMEM_FLOATS (OFF_MBAR + 4)
#define SMEM_BYTES  (SMEM_FLOATS * 4)     // ~204.3 KB -> 1 CTA/SM

__device__ __forceinline__ uint32_t smem_u32(const void* p) {
    uint32_t a;
    asm("{ .reg .u64 t; cvta.to.shared.u64 t, %1; cvt.u32.u64 %0, t; }"
        : "=r"(a) : "l"(p));
    return a;
}

__device__ __forceinline__ void mbar_wait(uint32_t mbar, uint32_t parity) {
    asm volatile(
        "{\n\t"
        ".reg .pred P;\n\t"
        "WL_%=: mbarrier.try_wait.parity.acquire.cta.shared::cta.b64 P, [%0], %1, 0x989680;\n\t"
        "@P bra WD_%=;\n\t"
        "bra WL_%=;\n\t"
        "WD_%=:\n\t"
        "}" :: "r"(mbar), "r"(parity) : "memory");
}

__device__ __forceinline__ void tma_load_half(uint32_t mbar, uint32_t dst,
                                              const char* src) {
    asm volatile("mbarrier.arrive.expect_tx.shared::cta.b64 _, [%0], %1;"
                 :: "r"(mbar), "r"((uint32_t)HALF_BYTES) : "memory");
    asm volatile(
        "cp.async.bulk.shared::cluster.global.mbarrier::complete_tx::bytes "
        "[%0], [%1], %2, [%3];"
        :: "r"(dst), "l"(src), "r"((uint32_t)HALF_BYTES), "r"(mbar)
        : "memory");
}

__device__ __forceinline__ void tma_store_half(char* dstg, uint32_t src) {
    asm volatile(
        "cp.async.bulk.global.shared::cta.bulk_group [%0], [%1], %2;"
        :: "l"(dstg), "r"(src), "r"((uint32_t)HALF_BYTES) : "memory");
    asm volatile("cp.async.bulk.commit_group;" ::: "memory");
}

__global__ __launch_bounds__(NTHR, 1)
void simam_dbuf_kernel(const float* __restrict__ x,
                       const float* __restrict__ weight,
                       const float* __restrict__ bias,
                       float* __restrict__ out)
{
    extern __shared__ float smem[];
    float*  s_s     = smem + OFF_S;
    float4* s_s4    = (float4*)s_s;
    float*  s_means = smem + OFF_MEANS;
    float*  s_red   = smem + OFF_RED;
    const uint32_t mbar0 = smem_u32(smem + OFF_MBAR);
    const uint32_t mbar1 = mbar0 + 8;
    const uint32_t sx0   = smem_u32(smem);

    const int tid  = threadIdx.x;
    const int w    = tid >> 5;
    const int lane = tid & 31;

    // ---- init + prologue load of first tile ----
    if (tid == 0) {
        asm volatile("mbarrier.init.shared::cta.b64 [%0], 1;" :: "r"(mbar0) : "memory");
        asm volatile("mbarrier.init.shared::cta.b64 [%0], 1;" :: "r"(mbar1) : "memory");
    }
    __syncthreads();
    if (tid == 0 && blockIdx.x < NTILE) {
        const char* xt = (const char*)(x + (size_t)blockIdx.x * TILE_FLOATS);
        tma_load_half(mbar0, sx0, xt);
        tma_load_half(mbar1, sx0 + HALF_BYTES, xt + HALF_BYTES);
    }

    int it = 0;
    for (int tile = blockIdx.x; tile < NTILE; tile += GRID, ++it) {
        const uint32_t par = (uint32_t)(it & 1);
        const int g = tile & 7;
        char* ot = (char*)(out + (size_t)tile * TILE_FLOATS);

        // ---- wait half0, means for channels [0,32) ----
        mbar_wait(mbar0, par);
        #pragma unroll
        for (int i = 0; i < 2; i++) {
            const int c = w + NW * i;                 // 0..31
            const float4* row = (const float4*)(smem + c * HWN);
            float cs = 0.f;
            #pragma unroll
            for (int k = 0; k < 7; k++) {
                const int j = lane + 32 * k;
                if (j < HW4) {
                    float4 v = row[j];
                    cs += (v.x + v.y) + (v.z + v.w);
                }
            }
            #pragma unroll
            for (int o = 16; o; o >>= 1) cs += __shfl_xor_sync(0xffffffffu, cs, o);
            if (lane == 0) s_means[c] = cs * (1.0f / HWN);
        }

        // ---- wait half1, means for channels [32,64) ----
        mbar_wait(mbar1, par);
        #pragma unroll
        for (int i = 0; i < 2; i++) {
            const int c = 32 + w + NW * i;            // 32..63
            const float4* row = (const float4*)(smem + c * HWN);
            float cs = 0.f;
            #pragma unroll
            for (int k = 0; k < 7; k++) {
                const int j = lane + 32 * k;
                if (j < HW4) {
                    float4 v = row[j];
                    cs += (v.x + v.y) + (v.z + v.w);
                }
            }
            #pragma unroll
            for (int o = 16; o; o >>= 1) cs += __shfl_xor_sync(0xffffffffu, cs, o);
            if (lane == 0) s_means[c] = cs * (1.0f / HWN);
        }
        __syncthreads();

        // ---- s-fold over all 64 channels (196 threads, column reads) ----
        float4 acc = make_float4(0.f, 0.f, 0.f, 0.f);
        float lsum = 0.f, lsq = 0.f;
        if (tid < HW4) {
            const float4* col = (const float4*)smem + tid;
            #pragma unroll 8
            for (int c = 0; c < CPG; c++) {
                const float  m = s_means[c];
                const float4 v = col[c * HW4];
                acc.x += m * v.x;
                acc.y += m * v.y;
                acc.z += m * v.z;
                acc.w += m * v.w;
            }
            lsum = (acc.x + acc.y) + (acc.z + acc.w);
            lsq  = acc.x * acc.x + acc.y * acc.y + acc.z * acc.z + acc.w * acc.w;
        }
        #pragma unroll
        for (int o = 16; o; o >>= 1) {
            lsum += __shfl_xor_sync(0xffffffffu, lsum, o);
            lsq  += __shfl_xor_sync(0xffffffffu, lsq,  o);
        }
        if (lane == 0) { s_red[w] = lsum; s_red[NW + w] = lsq; }
        __syncthreads();
        if (tid == 0) {
            float ts = 0.f, tq = 0.f;
            #pragma unroll
            for (int i = 0; i < NW; i++) { ts += s_red[i]; tq += s_red[NW + i]; }
            const float mu  = ts * (1.0f / HWN);
            const float var = tq * (1.0f / HWN) - mu * mu;
            s_red[32] = mu;
            s_red[33] = rsqrtf(var + EPS);
        }
        __syncthreads();
        {
            const float mu = s_red[32];
            const float rs = s_red[33];
            const float wg = weight[g];
            const float bb = bias[g];
            if (tid < HW4) {
                float4 gt;
                gt.x = 1.0f / (1.0f + __expf(-((acc.x - mu) * rs * wg + bb)));
                gt.y = 1.0f / (1.0f + __expf(-((acc.y - mu) * rs * wg + bb)));
                gt.z = 1.0f / (1.0f + __expf(-((acc.z - mu) * rs * wg + bb)));
                gt.w = 1.0f / (1.0f + __expf(-((acc.w - mu) * rs * wg + bb)));
                s_s4[tid] = gt;
            }
        }
        __syncthreads();

        const bool  hn = (tile + GRID) < NTILE;
        const char* xn = (const char*)(x + (size_t)(tile + GRID) * TILE_FLOATS);

        // ---- multiply half0 in place, TMA store half0 ----
        #pragma unroll
        for (int i = 0; i < 2; i++) {
            const int c = w + NW * i;
            float4* row = (float4*)(smem + c * HWN);
            #pragma unroll
            for (int k = 0; k < 7; k++) {
                const int j = lane + 32 * k;
                if (j < HW4) {
                    float4 v = row[j];
                    const float4 gt = s_s4[j];
                    v.x *= gt.x; v.y *= gt.y; v.z *= gt.z; v.w *= gt.w;
                    row[j] = v;
                }
            }
        }
        __syncthreads();
        if (tid == 0) {
            asm volatile("fence.proxy.async.shared::cta;" ::: "memory");
            tma_store_half(ot, sx0);
        }

        // ---- multiply half1 (overlaps store half0), TMA store half1 ----
        #pragma unroll
        for (int i = 0; i < 2; i++) {
            const int c = 32 + w + NW * i;
            float4* row = (float4*)(smem + c * HWN);
            #pragma unroll
            for (int k = 0; k < 7; k++) {
                const int j = lane + 32 * k;
                if (j < HW4) {
                    float4 v = row[j];
                    const float4 gt = s_s4[j];
                    v.x *= gt.x; v.y *= gt.y; v.z *= gt.z; v.w *= gt.w;
                    row[j] = v;
                }
            }
        }
        __syncthreads();
        if (tid == 0) {
            asm volatile("fence.proxy.async.shared::cta;" ::: "memory");
            tma_store_half(ot + HALF_BYTES, sx0 + HALF_BYTES);
            if (hn) {
                // refill each half as soon as its store has finished READING smem
                asm volatile("cp.async.bulk.wait_group.read 1;" ::: "memory");
                tma_load_half(mbar0, sx0, xn);
                asm volatile("cp.async.bulk.wait_group.read 0;" ::: "memory");
                tma_load_half(mbar1, sx0 + HALF_BYTES, xn + HALF_BYTES);
            }
        }
    }

    // drain outstanding bulk stores before exit
    if (tid == 0) {
        asm volatile("cp.async.bulk.wait_group 0;" ::: "memory");
    }
    __syncthreads();
}

extern "C" void kernel_launch(void* const* d_in, const int* in_sizes, int n_in,
                              void* d_out, int out_size)
{
    const float* x  = (const float*)d_in[0];
    const float* wt = (const float*)d_in[1];
    const float* bs = (const float*)d_in[2];
    float* out = (float*)d_out;

    cudaFuncSetAttribute(simam_dbuf_kernel,
                         cudaFuncAttributeMaxDynamicSharedMemorySize, SMEM_BYTES);
    simam_dbuf_kernel<<<GRID, NTHR, SMEM_BYTES>>>(x, wt, bs, out);
}